// round 2
// baseline (speedup 1.0000x reference)
#include <cuda_runtime.h>
#include <math.h>

#define M_SIZE 4096
#define NMODES 128
#define BATCH  32
#define CH     256
#define NROWS  (BATCH*CH)   // 8192
#define NC     (2*NMODES)   // 256 (re/im interleaved coefficient count)

// ---- device scratch (allocation-free: module globals) ----
__device__ float  g_basis[M_SIZE * NC];                 // [t][2m+reim]: cos / -sin   (4 MB)
__device__ float  g_xftT[NC * NROWS];                   // [c][row]                    (8 MB)
__device__ float2 g_wT[(size_t)NMODES * CH * CH];       // [m][i][o] complex          (64 MB)
__device__ float  g_oftT[NC * NROWS];                   // [c][row], scaled           (8 MB)

// ---------------------------------------------------------------------------
// Kernel 1: basis table. basis[t][2m] = cos(2*pi*m*t/M), basis[t][2m+1] = -sin(...)
// Angle reduced mod M before sincospif for full fp32 accuracy.
// ---------------------------------------------------------------------------
__global__ void k_basis() {
    int idx = blockIdx.x * blockDim.x + threadIdx.x;   // 0 .. 4096*128-1
    if (idx >= M_SIZE * NMODES) return;
    int t = idx >> 7;
    int m = idx & 127;
    int r = (t * m) & (M_SIZE - 1);
    float s, c;
    sincospif((float)r * (1.0f / 2048.0f), &s, &c);    // theta = 2*pi*r/4096
    g_basis[t * NC + 2 * m]     = c;
    g_basis[t * NC + 2 * m + 1] = -s;
}

// ---------------------------------------------------------------------------
// Kernel 2: weight transpose (o,i,m,2) -> (m,i,o) float2, coalesced both sides.
// ---------------------------------------------------------------------------
__global__ void k_wtrans(const float2* __restrict__ w2) {
    __shared__ float2 s[32][33];
    int i  = blockIdx.z;
    int o0 = blockIdx.x * 32;
    int m0 = blockIdx.y * 32;
    int tx = threadIdx.x & 31;
    int ty = threadIdx.x >> 5;   // 0..7
#pragma unroll
    for (int j = 0; j < 4; j++) {
        int ol = ty + j * 8;
        s[ol][tx] = w2[((size_t)(o0 + ol) * CH + i) * NMODES + m0 + tx];
    }
    __syncthreads();
#pragma unroll
    for (int j = 0; j < 4; j++) {
        int ml = ty + j * 8;
        g_wT[((size_t)(m0 + ml) * CH + i) * CH + o0 + tx] = s[tx][ml];
    }
}

// ---------------------------------------------------------------------------
// Kernel 3: forward DFT.  xftT[c][row] = sum_t x[row][t] * basis[t][c]
// Tile: 128 rows x 64 cols, K-chunk 16, micro 8x4, 256 threads.
// ---------------------------------------------------------------------------
__global__ void k_fwd(const float* __restrict__ x) {
    __shared__ float As[16][132];   // [k][row], padded
    __shared__ float Bs[16][68];    // [k][c],   padded
    int row0 = blockIdx.y * 128;
    int c0   = blockIdx.x * 64;
    int tid  = threadIdx.x;
    int cx   = tid & 15;            // col group: cols cx*4 .. +3
    int ty   = tid >> 4;            // row group: rows ty*8 .. +7
    float acc[8][4];
#pragma unroll
    for (int jr = 0; jr < 8; jr++)
#pragma unroll
        for (int jc = 0; jc < 4; jc++) acc[jr][jc] = 0.0f;

    for (int k0 = 0; k0 < M_SIZE; k0 += 16) {
        // A tile: x[row0+r][k0..k0+15], transposed into As[k][r]
#pragma unroll
        for (int it = 0; it < 2; it++) {
            int f  = tid + it * 256;
            int kq = f & 3;
            int r  = f >> 2;        // 0..127
            float4 v = *(const float4*)&x[(size_t)(row0 + r) * M_SIZE + k0 + kq * 4];
            As[kq * 4 + 0][r] = v.x;
            As[kq * 4 + 1][r] = v.y;
            As[kq * 4 + 2][r] = v.z;
            As[kq * 4 + 3][r] = v.w;
        }
        // B tile: basis[k0+kc][c0 .. c0+63]
        {
            int c4 = tid & 15;
            int kc = tid >> 4;
            float4 v = *(const float4*)&g_basis[(size_t)(k0 + kc) * NC + c0 + c4 * 4];
            *(float4*)&Bs[kc][c4 * 4] = v;
        }
        __syncthreads();
#pragma unroll
        for (int kc = 0; kc < 16; kc++) {
            float a[8], b[4];
            *(float4*)&a[0] = *(const float4*)&As[kc][ty * 8];
            *(float4*)&a[4] = *(const float4*)&As[kc][ty * 8 + 4];
            *(float4*)&b[0] = *(const float4*)&Bs[kc][cx * 4];
#pragma unroll
            for (int jr = 0; jr < 8; jr++)
#pragma unroll
                for (int jc = 0; jc < 4; jc++)
                    acc[jr][jc] += a[jr] * b[jc];
        }
        __syncthreads();
    }
    // epilogue: write transposed xftT[c][row]
#pragma unroll
    for (int jr = 0; jr < 8; jr++) {
        int row = row0 + ty * 8 + jr;
#pragma unroll
        for (int jc = 0; jc < 4; jc++)
            g_xftT[(size_t)(c0 + cx * 4 + jc) * NROWS + row] = acc[jr][jc];
    }
}

// ---------------------------------------------------------------------------
// Kernel 4: mode mixing. Grid (NMODES, 2); each block handles 16 batches of
// one mode. oftT[2m+..][b*CH+o] = scale * sum_i xft[b][i][m] * w[o][i][m].
// xft slab (16 batches x 256 ch complex = 32 KB) cached in static smem.
// scale = (m==0 ? 1 : 2)/M  (irfft Hermitian fold; imag(DC) killed by basis 0)
// ---------------------------------------------------------------------------
#define MIXB 16
__global__ void k_mix() {
    __shared__ float2 smix[MIXB * CH];   // 32 KB
    int m  = blockIdx.x;
    int b0 = blockIdx.y * MIXB;
    int o  = threadIdx.x;
    const float* xr = &g_xftT[(size_t)(2 * m) * NROWS + b0 * CH];
    const float* xi = &g_xftT[(size_t)(2 * m + 1) * NROWS + b0 * CH];
    for (int f = threadIdx.x; f < MIXB * CH; f += 256)
        smix[f] = make_float2(xr[f], xi[f]);
    __syncthreads();

    float accr[MIXB], acci[MIXB];
#pragma unroll
    for (int b = 0; b < MIXB; b++) { accr[b] = 0.0f; acci[b] = 0.0f; }

    const float2* wp = &g_wT[(size_t)m * CH * CH + o];
#pragma unroll 4
    for (int i = 0; i < CH; i++) {
        float2 w = wp[(size_t)i * CH];
#pragma unroll
        for (int b = 0; b < MIXB; b++) {
            float2 xv = smix[b * CH + i];
            accr[b] += xv.x * w.x - xv.y * w.y;
            acci[b] += xv.x * w.y + xv.y * w.x;
        }
    }
    float sc = (m == 0 ? 1.0f : 2.0f) * (1.0f / (float)M_SIZE);
#pragma unroll
    for (int b = 0; b < MIXB; b++) {
        g_oftT[(size_t)(2 * m)     * NROWS + (b0 + b) * CH + o] = accr[b] * sc;
        g_oftT[(size_t)(2 * m + 1) * NROWS + (b0 + b) * CH + o] = acci[b] * sc;
    }
}

// ---------------------------------------------------------------------------
// Kernel 5: inverse DFT + LeakyReLU + residual.
// out[row][t] = x[row][t] + leaky( sum_c oftT[c][row] * basis[t][c] )
// Tile: 128 rows x 64 t, K=256 chunked by 16, micro 8x4, 256 threads.
// ---------------------------------------------------------------------------
__global__ void k_inv(const float* __restrict__ x, float* __restrict__ out) {
    __shared__ float As[16][132];   // [c][row]
    __shared__ float Bs[16][68];    // [c][t]
    int row0 = blockIdx.y * 128;
    int t0   = blockIdx.x * 64;
    int tid  = threadIdx.x;
    int tx   = tid & 15;            // t group: t tx*4 .. +3
    int ty   = tid >> 4;            // row group: rows ty*8 .. +7
    float acc[8][4];
#pragma unroll
    for (int jr = 0; jr < 8; jr++)
#pragma unroll
        for (int jc = 0; jc < 4; jc++) acc[jr][jc] = 0.0f;

    for (int k0 = 0; k0 < NC; k0 += 16) {
        // A tile: oftT[k0+kc][row0 .. +127]  (already k-major -> direct vec copy)
#pragma unroll
        for (int it = 0; it < 2; it++) {
            int f  = tid + it * 256;
            int r4 = f & 31;
            int kc = f >> 5;        // 0..15
            float4 v = *(const float4*)&g_oftT[(size_t)(k0 + kc) * NROWS + row0 + r4 * 4];
            *(float4*)&As[kc][r4 * 4] = v;
        }
        // B tile: basis[t0+t][k0 .. +15], transposed into Bs[k][t]
        {
            int kq = tid & 3;
            int t  = tid >> 2;      // 0..63
            float4 v = *(const float4*)&g_basis[(size_t)(t0 + t) * NC + k0 + kq * 4];
            Bs[kq * 4 + 0][t] = v.x;
            Bs[kq * 4 + 1][t] = v.y;
            Bs[kq * 4 + 2][t] = v.z;
            Bs[kq * 4 + 3][t] = v.w;
        }
        __syncthreads();
#pragma unroll
        for (int kc = 0; kc < 16; kc++) {
            float a[8], b[4];
            *(float4*)&a[0] = *(const float4*)&As[kc][ty * 8];
            *(float4*)&a[4] = *(const float4*)&As[kc][ty * 8 + 4];
            *(float4*)&b[0] = *(const float4*)&Bs[kc][tx * 4];
#pragma unroll
            for (int jr = 0; jr < 8; jr++)
#pragma unroll
                for (int jc = 0; jc < 4; jc++)
                    acc[jr][jc] += a[jr] * b[jc];
        }
        __syncthreads();
    }
    // epilogue: residual + LeakyReLU(0.2), vectorized
#pragma unroll
    for (int jr = 0; jr < 8; jr++) {
        int row = row0 + ty * 8 + jr;
        size_t base = (size_t)row * M_SIZE + t0 + tx * 4;
        float4 xv = *(const float4*)&x[base];
        float4 r;
        float v0 = acc[jr][0], v1 = acc[jr][1], v2 = acc[jr][2], v3 = acc[jr][3];
        r.x = xv.x + (v0 >= 0.0f ? v0 : 0.2f * v0);
        r.y = xv.y + (v1 >= 0.0f ? v1 : 0.2f * v1);
        r.z = xv.z + (v2 >= 0.0f ? v2 : 0.2f * v2);
        r.w = xv.w + (v3 >= 0.0f ? v3 : 0.2f * v3);
        *(float4*)&out[base] = r;
    }
}

// ---------------------------------------------------------------------------
extern "C" void kernel_launch(void* const* d_in, const int* in_sizes, int n_in,
                              void* d_out, int out_size) {
    (void)in_sizes; (void)n_in; (void)out_size;
    const float*  x  = (const float*)d_in[0];
    const float2* w2 = (const float2*)d_in[1];
    float* out = (float*)d_out;

    k_basis<<<(M_SIZE * NMODES + 255) / 256, 256>>>();
    k_wtrans<<<dim3(CH / 32, NMODES / 32, CH), 256>>>(w2);
    k_fwd<<<dim3(NC / 64, NROWS / 128), 256>>>(x);
    k_mix<<<dim3(NMODES, BATCH / MIXB), 256>>>();
    k_inv<<<dim3(M_SIZE / 64, NROWS / 128), 256>>>(x, out);
}

// round 4
// speedup vs baseline: 1.9410x; 1.9410x over previous
#include <cuda_runtime.h>
#include <cuda_bf16.h>
#include <stdint.h>

#define M_SIZE 4096
#define NMODES 128
#define BATCH  32
#define CH     256
#define NROWS  (BATCH*CH)   // 8192
#define NC     (2*NMODES)   // 256

// ---------------- device scratch (allocation-free globals) ----------------
__device__ __nv_bfloat16 g_basis_h[(size_t)M_SIZE*NC];   // [t][c]  (inv B)
__device__ __nv_bfloat16 g_basis_l[(size_t)M_SIZE*NC];
__device__ __nv_bfloat16 g_basisT_h[(size_t)NC*M_SIZE];  // [c][t]  (fwd B)
__device__ __nv_bfloat16 g_basisT_l[(size_t)NC*M_SIZE];
__device__ float         g_xft[(size_t)NROWS*NC];        // [row][c] fp32
__device__ __nv_bfloat16 g_oft_h[(size_t)NROWS*NC];      // [row][c]
__device__ __nv_bfloat16 g_oft_l[(size_t)NROWS*NC];

// ---------------- helpers ----------------
__device__ __forceinline__ uint32_t smem_u32(const void* p) {
    uint32_t a;
    asm("{ .reg .u64 t; cvta.to.shared.u64 t, %1; cvt.u32.u64 %0, t; }" : "=r"(a) : "l"(p));
    return a;
}
#define SW(o) ((uint32_t)(o) ^ ((((uint32_t)(o)) >> 3) & 0x70))

#define CP16(d, s)  asm volatile("cp.async.cg.shared.global [%0], [%1], 16;" :: "r"(d), "l"(s))
#define CP_COMMIT() asm volatile("cp.async.commit_group;")
#define CP_WAIT0()  asm volatile("cp.async.wait_group 0;")

#define LDSM4(R, addr) \
    asm volatile("ldmatrix.sync.aligned.m8n8.x4.shared.b16 {%0,%1,%2,%3}, [%4];" \
        : "=r"((R)[0]), "=r"((R)[1]), "=r"((R)[2]), "=r"((R)[3]) : "r"(addr))

#define MMA4(C, A, b0, b1) \
    asm volatile("mma.sync.aligned.m16n8k16.row.col.f32.bf16.bf16.f32 " \
        "{%0,%1,%2,%3},{%4,%5,%6,%7},{%8,%9},{%0,%1,%2,%3};" \
        : "+f"((C)[0]), "+f"((C)[1]), "+f"((C)[2]), "+f"((C)[3]) \
        : "r"((A)[0]), "r"((A)[1]), "r"((A)[2]), "r"((A)[3]), "r"(b0), "r"(b1))

__device__ __forceinline__ void split_bf16(float v, __nv_bfloat16& h, __nv_bfloat16& l) {
    h = __float2bfloat16(v);
    l = __float2bfloat16(v - __bfloat162float(h));
}
__device__ __forceinline__ uint32_t pack2h(float a, float b) {
    __nv_bfloat162 t = __halves2bfloat162(__float2bfloat16(a), __float2bfloat16(b));
    return *(uint32_t*)&t;
}

// smem plane offsets within a 64KB buffer (A/B tiles are 128 rows x 128B)
#define P_AH 0
#define P_AL 16384
#define P_BH 32768
#define P_BL 49152
#define BUFB 65536
#define SMEM_GEMM (2*BUFB)

// ---------------------------------------------------------------------------
// Basis tables. theta = 2*pi*m*t/M; (cos, -sin) split hi/lo bf16.
// ---------------------------------------------------------------------------
__global__ void k_basis_a() {   // [t][c]
    int idx = blockIdx.x * blockDim.x + threadIdx.x;
    int t = idx >> 7, m = idx & 127;
    int r = (t * m) & (M_SIZE - 1);
    float s, c;
    sincospif((float)r * (1.0f / 2048.0f), &s, &c);
    __nv_bfloat16 ch, cl, sh, sl;
    split_bf16(c, ch, cl); split_bf16(-s, sh, sl);
    size_t b = (size_t)t * NC + 2 * m;
    *(__nv_bfloat162*)&g_basis_h[b] = __halves2bfloat162(ch, sh);
    *(__nv_bfloat162*)&g_basis_l[b] = __halves2bfloat162(cl, sl);
}
__global__ void k_basis_b() {   // [c][t]
    int idx = blockIdx.x * blockDim.x + threadIdx.x;
    int m = idx >> 12, t = idx & 4095;
    int r = (t * m) & (M_SIZE - 1);
    float s, c;
    sincospif((float)r * (1.0f / 2048.0f), &s, &c);
    __nv_bfloat16 ch, cl, sh, sl;
    split_bf16(c, ch, cl); split_bf16(-s, sh, sl);
    g_basisT_h[(size_t)(2*m)   * M_SIZE + t] = ch;
    g_basisT_h[(size_t)(2*m+1) * M_SIZE + t] = sh;
    g_basisT_l[(size_t)(2*m)   * M_SIZE + t] = cl;
    g_basisT_l[(size_t)(2*m+1) * M_SIZE + t] = sl;
}

// ---------------------------------------------------------------------------
// Forward DFT: g_xft[row][c] = sum_k x[row][k] * basisT[c][k]
// mma.sync bf16 split (hh+hl+lh). Block 128x128, 8 warps (64x32 each), K-chunk 64.
// ---------------------------------------------------------------------------
__global__ void __launch_bounds__(256, 1) k_fwd(const float* __restrict__ x) {
    extern __shared__ char sm[];
    uint32_t sb = smem_u32(sm);
    const int tid = threadIdx.x, lane = tid & 31, wid = tid >> 5;
    const int wm = wid & 1, wn = wid >> 1;
    const int row0 = blockIdx.x * 128;
    const int c0   = blockIdx.y * 128;

    uint32_t offA[4], offB[2];
#pragma unroll
    for (int mf = 0; mf < 4; mf++)
        offA[mf] = (wm*64 + mf*16 + (lane & 15)) * 128 + (lane >> 4) * 16;
#pragma unroll
    for (int p = 0; p < 2; p++)
        offB[p] = (wn*32 + p*16 + ((lane >> 4) << 3) + (lane & 7)) * 128
                + ((lane >> 3) & 1) * 16;

    float acc[4][4][4];
#pragma unroll
    for (int i = 0; i < 4; i++)
#pragma unroll
        for (int j = 0; j < 4; j++)
#pragma unroll
            for (int q = 0; q < 4; q++) acc[i][j][q] = 0.0f;

    // ---- preload chunk 0 into buffer 0 ----
    {
        const int k0 = 0;
        uint32_t bb = sb;
#pragma unroll
        for (int j = 0; j < 8; j++) {           // B planes via cp.async
            int f = tid + j * 256;
            int plane = f >> 10, r = (f >> 3) & 127, cb = f & 7;
            const __nv_bfloat16* src = (plane ? g_basisT_l : g_basisT_h)
                                     + (size_t)(c0 + r) * M_SIZE + k0 + cb * 8;
            CP16(bb + P_BH + plane * 16384 + SW(r * 128 + cb * 16), src);
        }
        CP_COMMIT();
#pragma unroll
        for (int it = 0; it < 8; it++) {        // A convert + STS
            int f = tid + it * 256;
            int r = f >> 4, q = f & 15;
            float4 v = *(const float4*)&x[(size_t)(row0 + r) * M_SIZE + k0 + q * 4];
            __nv_bfloat16 h0,l0,h1,l1,h2,l2,h3,l3;
            split_bf16(v.x,h0,l0); split_bf16(v.y,h1,l1);
            split_bf16(v.z,h2,l2); split_bf16(v.w,h3,l3);
            uint32_t off = SW(r * 128 + q * 8);
            __nv_bfloat162 th0 = __halves2bfloat162(h0,h1), th1 = __halves2bfloat162(h2,h3);
            __nv_bfloat162 tl0 = __halves2bfloat162(l0,l1), tl1 = __halves2bfloat162(l2,l3);
            uint2 uh = make_uint2(*(uint32_t*)&th0, *(uint32_t*)&th1);
            uint2 ul = make_uint2(*(uint32_t*)&tl0, *(uint32_t*)&tl1);
            *(uint2*)(sm + P_AH + off) = uh;
            *(uint2*)(sm + P_AL + off) = ul;
        }
        CP_WAIT0();
    }
    __syncthreads();

    const int NCHUNK = M_SIZE / 64;   // 64
    for (int cc = 0; cc < NCHUNK; cc++) {
        uint32_t bb = sb + (cc & 1) * BUFB;
        char*    nbp = sm + ((cc + 1) & 1) * BUFB;
        uint32_t nbb = sb + ((cc + 1) & 1) * BUFB;
        bool pf = (cc + 1 < NCHUNK);
        float4 va[8];
        int rpf[8], qpf[8];
        if (pf) {
            const int k1 = (cc + 1) * 64;
#pragma unroll
            for (int j = 0; j < 8; j++) {
                int f = tid + j * 256;
                int plane = f >> 10, r = (f >> 3) & 127, cb = f & 7;
                const __nv_bfloat16* src = (plane ? g_basisT_l : g_basisT_h)
                                         + (size_t)(c0 + r) * M_SIZE + k1 + cb * 8;
                CP16(nbb + P_BH + plane * 16384 + SW(r * 128 + cb * 16), src);
            }
            CP_COMMIT();
#pragma unroll
            for (int it = 0; it < 8; it++) {
                int f = tid + it * 256;
                rpf[it] = f >> 4; qpf[it] = f & 15;
                va[it] = *(const float4*)&x[(size_t)(row0 + rpf[it]) * M_SIZE + k1 + qpf[it] * 4];
            }
        }
        // ---- 4 x k16 MMA steps, 3 split products each ----
#pragma unroll
        for (int ks = 0; ks < 4; ks++) {
            uint32_t Af[4][4], Bh[2][4], Bo[2][4];
#pragma unroll
            for (int mf = 0; mf < 4; mf++) LDSM4(Af[mf], bb + P_AH + SW(offA[mf] + ks * 32));
#pragma unroll
            for (int p = 0; p < 2; p++)    LDSM4(Bh[p],  bb + P_BH + SW(offB[p] + ks * 32));
#pragma unroll
            for (int mf = 0; mf < 4; mf++)
#pragma unroll
                for (int nf = 0; nf < 4; nf++)
                    MMA4(acc[mf][nf], Af[mf], Bh[nf>>1][(nf&1)*2], Bh[nf>>1][(nf&1)*2+1]);
#pragma unroll
            for (int p = 0; p < 2; p++)    LDSM4(Bo[p],  bb + P_BL + SW(offB[p] + ks * 32));
#pragma unroll
            for (int mf = 0; mf < 4; mf++)
#pragma unroll
                for (int nf = 0; nf < 4; nf++)
                    MMA4(acc[mf][nf], Af[mf], Bo[nf>>1][(nf&1)*2], Bo[nf>>1][(nf&1)*2+1]);
#pragma unroll
            for (int mf = 0; mf < 4; mf++) LDSM4(Af[mf], bb + P_AL + SW(offA[mf] + ks * 32));
#pragma unroll
            for (int mf = 0; mf < 4; mf++)
#pragma unroll
                for (int nf = 0; nf < 4; nf++)
                    MMA4(acc[mf][nf], Af[mf], Bh[nf>>1][(nf&1)*2], Bh[nf>>1][(nf&1)*2+1]);
        }
        if (pf) {
#pragma unroll
            for (int it = 0; it < 8; it++) {
                float4 v = va[it];
                __nv_bfloat16 h0,l0,h1,l1,h2,l2,h3,l3;
                split_bf16(v.x,h0,l0); split_bf16(v.y,h1,l1);
                split_bf16(v.z,h2,l2); split_bf16(v.w,h3,l3);
                uint32_t off = SW(rpf[it] * 128 + qpf[it] * 8);
                __nv_bfloat162 th0 = __halves2bfloat162(h0,h1), th1 = __halves2bfloat162(h2,h3);
                __nv_bfloat162 tl0 = __halves2bfloat162(l0,l1), tl1 = __halves2bfloat162(l2,l3);
                uint2 uh = make_uint2(*(uint32_t*)&th0, *(uint32_t*)&th1);
                uint2 ul = make_uint2(*(uint32_t*)&tl0, *(uint32_t*)&tl1);
                *(uint2*)(nbp + P_AH + off) = uh;
                *(uint2*)(nbp + P_AL + off) = ul;
            }
        }
        CP_WAIT0();
        __syncthreads();
    }
    // ---- epilogue: write fp32 xft ----
#pragma unroll
    for (int mf = 0; mf < 4; mf++) {
        int row = row0 + wm*64 + mf*16 + (lane >> 2);
#pragma unroll
        for (int nf = 0; nf < 4; nf++) {
            int col = c0 + wn*32 + nf*8 + (lane & 3) * 2;
            *(float2*)&g_xft[(size_t)row * NC + col]       = make_float2(acc[mf][nf][0], acc[mf][nf][1]);
            *(float2*)&g_xft[(size_t)(row + 8) * NC + col] = make_float2(acc[mf][nf][2], acc[mf][nf][3]);
        }
    }
}

// ---------------------------------------------------------------------------
// Mode mixing, weight read IN ORIGINAL LAYOUT (o,i,m,2), coalesced over m.
// warp -> one o; lane -> one m; all 32 batches accumulated in registers.
// grid (32 o-blocks, 4 m-groups), 256 threads. Output: bf16 hi/lo planes, scaled.
// ---------------------------------------------------------------------------
__global__ void __launch_bounds__(256, 2) k_mix(const float2* __restrict__ w2) {
    extern __shared__ float2 Xs[];   // [8 i][32 b][32 m] = 8192 float2 = 64KB
    const int tid = threadIdx.x, lane = tid & 31, wid = tid >> 5;
    const int o  = blockIdx.x * 8 + wid;
    const int m0 = blockIdx.y * 32;
    const int m  = m0 + lane;

    float ar[BATCH], ai[BATCH];
#pragma unroll
    for (int b = 0; b < BATCH; b++) { ar[b] = 0.f; ai[b] = 0.f; }

    const float2* xftv = (const float2*)g_xft;   // [row][m] complex
    for (int it = 0; it < 32; it++) {
        const int i0 = it * 8;
        __syncthreads();
#pragma unroll
        for (int j = 0; j < 32; j++) {
            int f = tid + j * 256;
            int ii = f >> 10, b = (f >> 5) & 31, ml = f & 31;
            Xs[f] = xftv[(size_t)(b * CH + i0 + ii) * (NC/2) + m0 + ml];
        }
        __syncthreads();
#pragma unroll
        for (int ii = 0; ii < 8; ii++) {
            float2 w = w2[((size_t)o * CH + i0 + ii) * NMODES + m];
            const float2* xrow = &Xs[ii * 1024 + lane];
#pragma unroll
            for (int b = 0; b < BATCH; b++) {
                float2 xv = xrow[b * 32];
                ar[b] += xv.x * w.x - xv.y * w.y;
                ai[b] += xv.x * w.y + xv.y * w.x;
            }
        }
    }
    const float sc = (m == 0 ? 1.0f : 2.0f) * (1.0f / (float)M_SIZE);
#pragma unroll
    for (int b = 0; b < BATCH; b++) {
        float re = ar[b] * sc, im = ai[b] * sc;
        __nv_bfloat16 rh, rl, ih, il;
        split_bf16(re, rh, rl); split_bf16(im, ih, il);
        size_t idx = (size_t)(b * CH + o) * (NC/2) + m;
        ((__nv_bfloat162*)g_oft_h)[idx] = __halves2bfloat162(rh, ih);
        ((__nv_bfloat162*)g_oft_l)[idx] = __halves2bfloat162(rl, il);
    }
}

// ---------------------------------------------------------------------------
// Inverse DFT + LeakyReLU + residual.
// out[row][t] = x[row][t] + leaky( sum_c oft[row][c]*basis[t][c] )
// Same mma structure; A=oft planes, B=basis planes, K=256 (4 chunks), all cp.async.
// ---------------------------------------------------------------------------
__global__ void __launch_bounds__(256, 1) k_inv(const float* __restrict__ x,
                                                float* __restrict__ out) {
    extern __shared__ char sm[];
    uint32_t sb = smem_u32(sm);
    const int tid = threadIdx.x, lane = tid & 31, wid = tid >> 5;
    const int wm = wid & 1, wn = wid >> 1;
    const int t0   = blockIdx.x * 128;
    const int row0 = blockIdx.y * 128;

    uint32_t offA[4], offB[2];
#pragma unroll
    for (int mf = 0; mf < 4; mf++)
        offA[mf] = (wm*64 + mf*16 + (lane & 15)) * 128 + (lane >> 4) * 16;
#pragma unroll
    for (int p = 0; p < 2; p++)
        offB[p] = (wn*32 + p*16 + ((lane >> 4) << 3) + (lane & 7)) * 128
                + ((lane >> 3) & 1) * 16;

    float acc[4][4][4];
#pragma unroll
    for (int i = 0; i < 4; i++)
#pragma unroll
        for (int j = 0; j < 4; j++)
#pragma unroll
            for (int q = 0; q < 4; q++) acc[i][j][q] = 0.0f;

    // preload chunk 0
    {
        const int k0 = 0;
#pragma unroll
        for (int j = 0; j < 8; j++) {
            int f = tid + j * 256;
            int plane = f >> 10, r = (f >> 3) & 127, cb = f & 7;
            const __nv_bfloat16* src = (plane ? g_oft_l : g_oft_h)
                                     + (size_t)(row0 + r) * NC + k0 + cb * 8;
            CP16(sb + P_AH + plane * 16384 + SW(r * 128 + cb * 16), src);
        }
#pragma unroll
        for (int j = 0; j < 8; j++) {
            int f = tid + j * 256;
            int plane = f >> 10, r = (f >> 3) & 127, cb = f & 7;
            const __nv_bfloat16* src = (plane ? g_basis_l : g_basis_h)
                                     + (size_t)(t0 + r) * NC + k0 + cb * 8;
            CP16(sb + P_BH + plane * 16384 + SW(r * 128 + cb * 16), src);
        }
        CP_COMMIT();
        CP_WAIT0();
    }
    __syncthreads();

    const int NCHUNK = NC / 64;   // 4
    for (int cc = 0; cc < NCHUNK; cc++) {
        uint32_t bb  = sb + (cc & 1) * BUFB;
        uint32_t nbb = sb + ((cc + 1) & 1) * BUFB;
        if (cc + 1 < NCHUNK) {
            const int k1 = (cc + 1) * 64;
#pragma unroll
            for (int j = 0; j < 8; j++) {
                int f = tid + j * 256;
                int plane = f >> 10, r = (f >> 3) & 127, cb = f & 7;
                const __nv_bfloat16* src = (plane ? g_oft_l : g_oft_h)
                                         + (size_t)(row0 + r) * NC + k1 + cb * 8;
                CP16(nbb + P_AH + plane * 16384 + SW(r * 128 + cb * 16), src);
            }
#pragma unroll
            for (int j = 0; j < 8; j++) {
                int f = tid + j * 256;
                int plane = f >> 10, r = (f >> 3) & 127, cb = f & 7;
                const __nv_bfloat16* src = (plane ? g_basis_l : g_basis_h)
                                         + (size_t)(t0 + r) * NC + k1 + cb * 8;
                CP16(nbb + P_BH + plane * 16384 + SW(r * 128 + cb * 16), src);
            }
            CP_COMMIT();
        }
#pragma unroll
        for (int ks = 0; ks < 4; ks++) {
            uint32_t Af[4][4], Bh[2][4], Bo[2][4];
#pragma unroll
            for (int mf = 0; mf < 4; mf++) LDSM4(Af[mf], bb + P_AH + SW(offA[mf] + ks * 32));
#pragma unroll
            for (int p = 0; p < 2; p++)    LDSM4(Bh[p],  bb + P_BH + SW(offB[p] + ks * 32));
#pragma unroll
            for (int mf = 0; mf < 4; mf++)
#pragma unroll
                for (int nf = 0; nf < 4; nf++)
                    MMA4(acc[mf][nf], Af[mf], Bh[nf>>1][(nf&1)*2], Bh[nf>>1][(nf&1)*2+1]);
#pragma unroll
            for (int p = 0; p < 2; p++)    LDSM4(Bo[p],  bb + P_BL + SW(offB[p] + ks * 32));
#pragma unroll
            for (int mf = 0; mf < 4; mf++)
#pragma unroll
                for (int nf = 0; nf < 4; nf++)
                    MMA4(acc[mf][nf], Af[mf], Bo[nf>>1][(nf&1)*2], Bo[nf>>1][(nf&1)*2+1]);
#pragma unroll
            for (int mf = 0; mf < 4; mf++) LDSM4(Af[mf], bb + P_AL + SW(offA[mf] + ks * 32));
#pragma unroll
            for (int mf = 0; mf < 4; mf++)
#pragma unroll
                for (int nf = 0; nf < 4; nf++)
                    MMA4(acc[mf][nf], Af[mf], Bh[nf>>1][(nf&1)*2], Bh[nf>>1][(nf&1)*2+1]);
        }
        CP_WAIT0();
        __syncthreads();
    }
    // epilogue: LeakyReLU + residual
#pragma unroll
    for (int mf = 0; mf < 4; mf++) {
        int row = row0 + wm*64 + mf*16 + (lane >> 2);
#pragma unroll
        for (int nf = 0; nf < 4; nf++) {
            int tc = t0 + wn*32 + nf*8 + (lane & 3) * 2;
#pragma unroll
            for (int h = 0; h < 2; h++) {
                size_t base = (size_t)(row + h * 8) * M_SIZE + tc;
                float2 xv = *(const float2*)&x[base];
                float v0 = acc[mf][nf][h*2], v1 = acc[mf][nf][h*2+1];
                float2 rv;
                rv.x = xv.x + (v0 >= 0.f ? v0 : 0.2f * v0);
                rv.y = xv.y + (v1 >= 0.f ? v1 : 0.2f * v1);
                *(float2*)&out[base] = rv;
            }
        }
    }
}

// ---------------------------------------------------------------------------
extern "C" void kernel_launch(void* const* d_in, const int* in_sizes, int n_in,
                              void* d_out, int out_size) {
    (void)in_sizes; (void)n_in; (void)out_size;
    const float*  x  = (const float*)d_in[0];
    const float2* w2 = (const float2*)d_in[1];
    float* out = (float*)d_out;

    cudaFuncSetAttribute(k_fwd, cudaFuncAttributeMaxDynamicSharedMemorySize, SMEM_GEMM);
    cudaFuncSetAttribute(k_inv, cudaFuncAttributeMaxDynamicSharedMemorySize, SMEM_GEMM);
    cudaFuncSetAttribute(k_mix, cudaFuncAttributeMaxDynamicSharedMemorySize, 65536);

    k_basis_a<<<(M_SIZE * NMODES) / 256, 256>>>();
    k_basis_b<<<(M_SIZE * NMODES) / 256, 256>>>();
    k_fwd<<<dim3(NROWS / 128, NC / 128), 256, SMEM_GEMM>>>(x);
    k_mix<<<dim3(CH / 8, NMODES / 32), 256, 65536>>>(w2);
    k_inv<<<dim3(M_SIZE / 128, NROWS / 128), 256, SMEM_GEMM>>>(x, out);
}